// round 13
// baseline (speedup 1.0000x reference)
#include <cuda_runtime.h>
#include <cuda_fp16.h>
#include <cstdint>
#include <cstddef>

#define Bb 64
#define Ss 512
#define Zz 1024
#define H2 256
#define ZS (Zz*Ss)

// ---------------- static scratch ----------------
__device__ __half g_P[(size_t)Bb*ZS];     // 67MB: exp(lc0 + bout) fp16
__device__ float g_v2[Bb*H2];
__device__ float g_elp2[Bb*Ss];
__device__ float g_u[Bb*Ss];
__device__ float g_lp1[Zz];
__device__ float g_elp1[Zz];
__device__ float g_iR[Bb*Zz];
__device__ float g_cph[2][Bb*Ss];         // per-half column partials
__device__ int   g_bar[Bb];               // cross-CTA barrier counters

// smem layout for k_gemm (dynamic):
//   [0, 66560)        sA: float[64][260]  (A staged, conflict-free frag reads)
//   [66560, 108800)   sB: float[5][8][264] (B 5-stage)  UNION  sO: __half2[64][132]
#define SMEM_B_OFF      66560
#define SMEM_TOTAL_GEMM 108800

// ---------------- zero barrier counters (each graph replay) ----------------
__global__ void k_zero() { g_bar[threadIdx.x] = 0; }

// ---------------- prior: lp1 = log_softmax(prior) ----------------
__global__ void k_prior(const float* __restrict__ prior) {
    __shared__ float red[1024];
    int tid = threadIdx.x;
    float x = prior[tid];
    red[tid] = x; __syncthreads();
    for (int o = 512; o > 0; o >>= 1) { if (tid < o) red[tid] = fmaxf(red[tid], red[tid+o]); __syncthreads(); }
    float m = red[0]; __syncthreads();
    float e = __expf(x - m);
    red[tid] = e; __syncthreads();
    for (int o = 512; o > 0; o >>= 1) { if (tid < o) red[tid] += red[tid+o]; __syncthreads(); }
    float lse = m + __logf(red[0]);
    float lp1 = x - lse;
    g_lp1[tid] = lp1;
    g_elp1[tid] = __expf(lp1);
}

// ---------------- MLP ----------------
__global__ void k_mlp(const float* __restrict__ sl, const float* __restrict__ W1,
                      const float* __restrict__ b1, const float* __restrict__ W2,
                      const float* __restrict__ b2) {
    __shared__ float sv[Ss];
    __shared__ float v1s[Ss];
    __shared__ float red[Ss];
    int b = blockIdx.x, tid = threadIdx.x;
    float x = sl[b*Ss + tid];
    red[tid] = x; __syncthreads();
    for (int o = 256; o > 0; o >>= 1) { if (tid < o) red[tid] = fmaxf(red[tid], red[tid+o]); __syncthreads(); }
    float m = red[0]; __syncthreads();
    float e = __expf(x - m);
    red[tid] = e; __syncthreads();
    for (int o = 256; o > 0; o >>= 1) { if (tid < o) red[tid] += red[tid+o]; __syncthreads(); }
    float inv = 1.0f / red[0];
    float v = e * inv;
    sv[tid] = v;
    g_elp2[b*Ss + tid] = v;
    __syncthreads();
    float acc = b1[tid];
    #pragma unroll 4
    for (int s = 0; s < Ss; s++) acc = fmaf(sv[s], W1[s*512 + tid], acc);
    v1s[tid] = 1.0f / (1.0f + __expf(-acc));
    __syncthreads();
    if (tid < H2) {
        float a2 = b2[tid];
        #pragma unroll 4
        for (int h = 0; h < 512; h++) a2 = fmaf(v1s[h], W2[h*H2 + tid], a2);
        g_v2[b*H2 + tid] = 1.0f / (1.0f + __expf(-a2));
    }
}

// ---------------- GEMM: P = exp(v2 @ Wout + bout) -> fp16, cp.async 5-stage, A in smem ----------------
__device__ __forceinline__ void mma8(float* c, uint32_t a0, uint32_t a1, uint32_t a2, uint32_t a3,
                                     uint32_t b0, uint32_t b1) {
    asm volatile(
        "mma.sync.aligned.m16n8k8.row.col.f32.tf32.tf32.f32 "
        "{%0,%1,%2,%3},{%4,%5,%6,%7},{%8,%9},{%0,%1,%2,%3};"
        : "+f"(c[0]), "+f"(c[1]), "+f"(c[2]), "+f"(c[3])
        : "r"(a0), "r"(a1), "r"(a2), "r"(a3), "r"(b0), "r"(b1));
}

__device__ __forceinline__ void cp16(uint32_t saddr, const void* gptr) {
    asm volatile("cp.async.cg.shared.global [%0], [%1], 16;" :: "r"(saddr), "l"(gptr));
}

__global__ void __launch_bounds__(256, 2) k_gemm(const float* __restrict__ Wout,
                                                 const float* __restrict__ bout) {
    extern __shared__ __align__(16) unsigned char smem_raw[];
    float* sA = (float*)smem_raw;                                   // [64][260]
    float (*sB)[8][264] = (float (*)[8][264])(smem_raw + SMEM_B_OFF);
    __half2 (*sO)[132] = (__half2 (*)[132])(smem_raw + SMEM_B_OFF);
    uint32_t sbbase = (uint32_t)__cvta_generic_to_shared(smem_raw + SMEM_B_OFF);

    int tid = threadIdx.x, wid = tid >> 5, lane = tid & 31;
    int gid = lane >> 2, tig = lane & 3;
    int n0 = blockIdx.x * 256;

    int kr = tid >> 5;            // 0..7 k-row within stage
    int c0 = (tid & 31) * 8;      // 0..248 col

    // stage A once: sA[m][k], row stride 260 (bank = gid*4+tig -> conflict-free frags)
    #pragma unroll
    for (int ii = 0; ii < 64; ii++) {
        int idx = ii*256 + tid;
        int m = idx >> 8, k = idx & 255;
        sA[m*260 + k] = g_v2[idx];
    }

    float c[4][4][4];
    #pragma unroll
    for (int mt = 0; mt < 4; mt++)
        #pragma unroll
        for (int nt = 0; nt < 4; nt++)
            { c[mt][nt][0]=0.f; c[mt][nt][1]=0.f; c[mt][nt][2]=0.f; c[mt][nt][3]=0.f; }

    // prologue: issue stages 0..3
    #pragma unroll
    for (int s = 0; s < 4; s++) {
        const float* src = Wout + (size_t)(s*8 + kr)*ZS + n0 + c0;
        uint32_t dst = sbbase + (uint32_t)((s*8 + kr)*264 + c0) * 4u;
        cp16(dst, src);
        cp16(dst + 16, src + 4);
        asm volatile("cp.async.commit_group;");
    }
    __syncthreads();   // sA staged before any warp reads it

    for (int j = 0; j < 32; j++) {
        // tail-exact waits: stage j is the (j+1)-th committed group.
        // committed before wait = 4 + min(j,28) -> allowed pending = 3/2/1/0.
        if (j < 29)       asm volatile("cp.async.wait_group 3;");
        else if (j == 29) asm volatile("cp.async.wait_group 2;");
        else if (j == 30) asm volatile("cp.async.wait_group 1;");
        else              asm volatile("cp.async.wait_group 0;");
        __syncthreads();
        if (j + 4 < 32) {
            int s = (j + 4) % 5;
            const float* src = Wout + (size_t)((j+4)*8 + kr)*ZS + n0 + c0;
            uint32_t dst = sbbase + (uint32_t)((s*8 + kr)*264 + c0) * 4u;
            cp16(dst, src);
            cp16(dst + 16, src + 4);
            asm volatile("cp.async.commit_group;");
        }
        int buf = j % 5;
        int k0 = j * 8;
        uint32_t a0[4], a1[4], a2[4], a3[4];
        #pragma unroll
        for (int mt = 0; mt < 4; mt++) {
            a0[mt] = __float_as_uint(sA[(mt*16+gid  )*260 + k0 + tig    ]);
            a1[mt] = __float_as_uint(sA[(mt*16+gid+8)*260 + k0 + tig    ]);
            a2[mt] = __float_as_uint(sA[(mt*16+gid  )*260 + k0 + tig + 4]);
            a3[mt] = __float_as_uint(sA[(mt*16+gid+8)*260 + k0 + tig + 4]);
        }
        #pragma unroll
        for (int nt = 0; nt < 4; nt++) {
            int colb = wid*32 + nt*8 + gid;
            uint32_t b0 = __float_as_uint(sB[buf][tig  ][colb]);
            uint32_t b1 = __float_as_uint(sB[buf][tig+4][colb]);
            #pragma unroll
            for (int mt = 0; mt < 4; mt++)
                mma8(c[mt][nt], a0[mt], a1[mt], a2[mt], a3[mt], b0, b1);
        }
    }
    __syncthreads();   // all reads of sB done before epilogue reuses smem

    // epilogue: exp(c + bout) -> half2, stage in smem, coalesced copy out
    #pragma unroll
    for (int nt = 0; nt < 4; nt++) {
        int colp = wid*16 + nt*4 + tig;
        float bo0 = bout[n0 + colp*2];
        float bo1 = bout[n0 + colp*2 + 1];
        #pragma unroll
        for (int mt = 0; mt < 4; mt++) {
            int r0 = mt*16 + gid;
            sO[r0  ][colp] = __floats2half2_rn(__expf(c[mt][nt][0]+bo0), __expf(c[mt][nt][1]+bo1));
            sO[r0+8][colp] = __floats2half2_rn(__expf(c[mt][nt][2]+bo0), __expf(c[mt][nt][3]+bo1));
        }
    }
    __syncthreads();
    int r = tid >> 2;
    #pragma unroll
    for (int pass = 0; pass < 8; pass++) {
        int u = (tid & 3) + 4*pass;
        uint4 v = *(uint4*)&sO[r][u*4];
        ((uint4*)(g_P + (size_t)r*ZS + n0))[u] = v;
    }
}

// ---------------- helpers ----------------
__device__ __forceinline__ void unpack8(uint4 q, float* p) {
    float2 f;
    f = __half22float2(*(__half2*)&q.x); p[0]=f.x; p[1]=f.y;
    f = __half22float2(*(__half2*)&q.y); p[2]=f.x; p[3]=f.y;
    f = __half22float2(*(__half2*)&q.z); p[4]=f.x; p[5]=f.y;
    f = __half22float2(*(__half2*)&q.w); p[6]=f.x; p[7]=f.y;
}

// ---------------- persistent Sinkhorn, 2 CTAs/batch with cross-CTA barrier ----------------
__global__ void __launch_bounds__(512, 1) k_sinkp2() {
    __shared__ float s_ew[Ss];
    __shared__ float s_col[Ss];
    __shared__ float s_elp2[Ss];
    __shared__ float s_elp1h[Ss];
    __shared__ float s_part[16][Ss];
    __shared__ float s_red[Ss];

    int b = blockIdx.x >> 1, half = blockIdx.x & 1;
    int tid = threadIdx.x;
    int w = tid >> 5, lane = tid & 31;

    s_elp2[tid]  = g_elp2[b*Ss + tid];
    s_elp1h[tid] = g_elp1[half*512 + tid];
    __syncthreads();

    const uint4* Pb = (const uint4*)(g_P + (size_t)b*ZS);
    float my_part = 0.f;

    for (int it = 0; it <= 10; it++) {
        float ew;
        if (it == 0) ew = 1.0f;
        else {
            float other = g_cph[1 - half][b*Ss + tid];
            s_col[tid] = my_part + other;
            ew = s_elp2[tid] / (my_part + other);
        }
        s_ew[tid] = ew;
        __syncthreads();

        float ewr[16], colacc[16];
        #pragma unroll
        for (int i = 0; i < 8; i++) {
            ewr[i]   = s_ew[8*lane + i];
            ewr[8+i] = s_ew[256 + 8*lane + i];
            colacc[i] = 0.f; colacc[8+i] = 0.f;
        }
        // 4 batches x 8 rows: 16 LDG.128 in flight per warp for latency cover
        #pragma unroll
        for (int rq = 0; rq < 4; rq++) {
            int zl = w*32 + rq*8;
            uint4 q[16];
            #pragma unroll
            for (int rr = 0; rr < 8; rr++) {
                const uint4* row = Pb + (size_t)(half*512 + zl + rr)*64;
                q[2*rr]   = row[lane];
                q[2*rr+1] = row[lane + 32];
            }
            #pragma unroll
            for (int rr = 0; rr < 8; rr++) {
                float p[16];
                unpack8(q[2*rr], p); unpack8(q[2*rr+1], p+8);
                float rs = 0.f;
                #pragma unroll
                for (int i = 0; i < 16; i++) rs = fmaf(p[i], ewr[i], rs);
                #pragma unroll
                for (int o = 16; o > 0; o >>= 1) rs += __shfl_xor_sync(0xFFFFFFFFu, rs, o);
                float irs = 1.0f / rs;
                int zg = half*512 + zl + rr;
                if (it == 10 && lane == 0) g_iR[b*Zz + zg] = irs;
                float ea = s_elp1h[zl + rr] * irs;
                #pragma unroll
                for (int i = 0; i < 16; i++) colacc[i] = fmaf(p[i], ea, colacc[i]);
            }
        }
        *(float4*)&s_part[w][8*lane]           = make_float4(colacc[0],  colacc[1],  colacc[2],  colacc[3]);
        *(float4*)&s_part[w][8*lane + 4]       = make_float4(colacc[4],  colacc[5],  colacc[6],  colacc[7]);
        *(float4*)&s_part[w][256 + 8*lane]     = make_float4(colacc[8],  colacc[9],  colacc[10], colacc[11]);
        *(float4*)&s_part[w][256 + 8*lane + 4] = make_float4(colacc[12], colacc[13], colacc[14], colacc[15]);
        __syncthreads();
        float sum = 0.f;
        #pragma unroll
        for (int ww = 0; ww < 16; ww++) sum += s_part[ww][tid];
        my_part = sum;
        g_cph[half][b*Ss + tid] = sum;
        __syncthreads();
        // cross-CTA barrier: release-increment + acquire-poll (no full membar RMW spin)
        if (tid == 0) {
            int target = 2 * (it + 1);
            asm volatile("red.release.gpu.global.add.s32 [%0], 1;"
                         :: "l"(&g_bar[b]) : "memory");
            int v;
            do {
                asm volatile("ld.acquire.gpu.global.s32 %0, [%1];"
                             : "=r"(v) : "l"(&g_bar[b]) : "memory");
            } while (v < target);
        }
        __syncthreads();
    }

    float other = g_cph[1 - half][b*Ss + tid];
    float colsum = my_part + other;
    float A = s_elp2[tid] / (s_ew[tid] * colsum);
    s_red[tid] = A; __syncthreads();
    for (int o = 256; o > 0; o >>= 1) { if (tid < o) s_red[tid] = fmaxf(s_red[tid], s_red[tid+o]); __syncthreads(); }
    float mx = s_red[0];
    if (half == 0) g_u[b*Ss + tid] = s_ew[tid] * A / mx;
}

// ---------------- fused keep+final ----------------
__global__ void __launch_bounds__(256, 4) k_kf(float* __restrict__ out) {
    int b = blockIdx.y, chunk = blockIdx.x, tid = threadIdx.x;
    __shared__ float s_u[Ss];
    __shared__ float s_e2[Ss];
    #pragma unroll
    for (int h = 0; h < 2; h++) {
        int s = tid + 256*h;
        s_u[s]  = g_u[b*Ss + s];
        s_e2[s] = g_elp2[b*Ss + s];
    }
    __syncthreads();
    int wid = tid >> 5, lane = tid & 31;
    float ur[16], er[16];
    #pragma unroll
    for (int i = 0; i < 8; i++) {
        ur[i]   = s_u[8*lane + i];    ur[8+i] = s_u[256 + 8*lane + i];
        er[i]   = s_e2[8*lane + i];   er[8+i] = s_e2[256 + 8*lane + i];
    }
    const uint4* Pb = (const uint4*)(g_P + (size_t)b*ZS);
    float* Ob = out + (size_t)b*ZS;
    #pragma unroll
    for (int r = 0; r < 8; r++) {
        int z = chunk*64 + wid*8 + r;
        uint4 q0 = Pb[(size_t)z*64 + lane];
        uint4 q1 = Pb[(size_t)z*64 + 32 + lane];
        float p[16];
        unpack8(q0, p); unpack8(q1, p+8);
        float ks = 0.f;
        #pragma unroll
        for (int i = 0; i < 16; i++) ks = fmaf(p[i], ur[i], ks);
        #pragma unroll
        for (int o = 16; o > 0; o >>= 1) ks += __shfl_xor_sync(0xFFFFFFFFu, ks, o);
        float iR = g_iR[b*Zz + z];
        float K = iR * ks;
        float eres = fmaxf(0.f, 1.f - K);
        float l1 = g_lp1[z];
        float v[16];
        #pragma unroll
        for (int i = 0; i < 16; i++)
            v[i] = l1 + __logf(fmaf(p[i], ur[i]*iR, eres*er[i]));
        float* o0 = Ob + (size_t)z*512 + 8*lane;
        float* o1 = o0 + 256;
        *(float4*)(o0    ) = make_float4(v[0], v[1], v[2], v[3]);
        *(float4*)(o0 + 4) = make_float4(v[4], v[5], v[6], v[7]);
        *(float4*)(o1    ) = make_float4(v[8], v[9], v[10], v[11]);
        *(float4*)(o1 + 4) = make_float4(v[12], v[13], v[14], v[15]);
    }
}

// ---------------- launch ----------------
extern "C" void kernel_launch(void* const* d_in, const int* in_sizes, int n_in,
                              void* d_out, int out_size) {
    const float* s_logits = (const float*)d_in[0];
    const float* W1   = (const float*)d_in[1];
    const float* b1   = (const float*)d_in[2];
    const float* W2   = (const float*)d_in[3];
    const float* b2   = (const float*)d_in[4];
    const float* Wout = (const float*)d_in[5];
    const float* bout = (const float*)d_in[6];
    const float* prior= (const float*)d_in[7];
    float* out = (float*)d_out;
    (void)in_sizes; (void)n_in; (void)out_size;

    cudaFuncSetAttribute(k_gemm, cudaFuncAttributeMaxDynamicSharedMemorySize, SMEM_TOTAL_GEMM);

    k_zero<<<1, Bb>>>();
    k_prior<<<1, 1024>>>(prior);
    k_mlp<<<Bb, 512>>>(s_logits, W1, b1, W2, b2);
    k_gemm<<<2048, 256, SMEM_TOTAL_GEMM>>>(Wout, bout);
    k_sinkp2<<<2*Bb, 512>>>();
    k_kf<<<dim3(16, Bb), 256>>>(out);
}